// round 2
// baseline (speedup 1.0000x reference)
#include <cuda_runtime.h>

// 3D soft-argmax: per (n,j), softmax over 64^3 volume, expectation of (w,h,d).
// One-pass online softmax, one CTA per (n,j) pair.

#define VOL_F4   65536      // 64*64*64 / 4 float4s per pair
#define THREADS  512
#define NEG_BIG  (-3.402823466e38f)

__device__ __forceinline__ void accum4(float4 v, int idx, float m,
                                       float& s, float& sx, float& sy, float& sz) {
    // idx = float4 index within the 64^3 volume. element linear = idx*4.
    // w0 = (idx*4) & 63, h = (idx*4 >> 6) & 63, d = (idx*4) >> 12
    float e0 = __expf(v.x - m);
    float e1 = __expf(v.y - m);
    float e2 = __expf(v.z - m);
    float e3 = __expf(v.w - m);
    float es = (e0 + e1) + (e2 + e3);
    float w0 = (float)((idx & 15) << 2);
    float h  = (float)((idx >> 4) & 63);
    float d  = (float)(idx >> 10);
    s  += es;
    sx += es * w0 + (e1 + 2.0f * e2 + 3.0f * e3);
    sy += es * h;
    sz += es * d;
}

__device__ __forceinline__ void online_merge(float& m, float& s, float& sx, float& sy, float& sz,
                                             float om, float os, float osx, float osy, float osz) {
    float nm = fmaxf(m, om);
    float ca = __expf(m  - nm);
    float cb = __expf(om - nm);
    s  = s  * ca + os  * cb;
    sx = sx * ca + osx * cb;
    sy = sy * ca + osy * cb;
    sz = sz * ca + osz * cb;
    m = nm;
}

__global__ __launch_bounds__(THREADS)
void soft_argmax3d_kernel(const float* __restrict__ in, float* __restrict__ out) {
    const int b = blockIdx.x;  // n*24 + j
    const float4* __restrict__ base =
        reinterpret_cast<const float4*>(in) + (size_t)b * VOL_F4;
    const int tid = threadIdx.x;

    float m = NEG_BIG, s = 0.0f, sx = 0.0f, sy = 0.0f, sz = 0.0f;

    // 65536 float4s / (512 threads * 4 f4 per iter) = 32 iterations
    #pragma unroll 4
    for (int it = 0; it < VOL_F4; it += THREADS * 4) {
        int i0 = it + tid;
        // 4 coalesced float4 loads -> MLP=4 per thread
        float4 v0 = base[i0];
        float4 v1 = base[i0 + THREADS];
        float4 v2 = base[i0 + 2 * THREADS];
        float4 v3 = base[i0 + 3 * THREADS];

        // chunk max over 16 values (cheap FMNMX tree)
        float c0 = fmaxf(fmaxf(v0.x, v0.y), fmaxf(v0.z, v0.w));
        float c1 = fmaxf(fmaxf(v1.x, v1.y), fmaxf(v1.z, v1.w));
        float c2 = fmaxf(fmaxf(v2.x, v2.y), fmaxf(v2.z, v2.w));
        float c3 = fmaxf(fmaxf(v3.x, v3.y), fmaxf(v3.z, v3.w));
        float cm = fmaxf(fmaxf(c0, c1), fmaxf(c2, c3));

        // one rescale per 16 elements
        float nm = fmaxf(m, cm);
        float corr = __expf(m - nm);   // ==1 when no new max; ==0 on first iter
        s *= corr; sx *= corr; sy *= corr; sz *= corr;
        m = nm;

        accum4(v0, i0,               m, s, sx, sy, sz);
        accum4(v1, i0 +     THREADS, m, s, sx, sy, sz);
        accum4(v2, i0 + 2 * THREADS, m, s, sx, sy, sz);
        accum4(v3, i0 + 3 * THREADS, m, s, sx, sy, sz);
    }

    // ---- warp reduction (xor butterfly, online merge) ----
    #pragma unroll
    for (int off = 16; off > 0; off >>= 1) {
        float om  = __shfl_xor_sync(0xFFFFFFFFu, m,  off);
        float os  = __shfl_xor_sync(0xFFFFFFFFu, s,  off);
        float osx = __shfl_xor_sync(0xFFFFFFFFu, sx, off);
        float osy = __shfl_xor_sync(0xFFFFFFFFu, sy, off);
        float osz = __shfl_xor_sync(0xFFFFFFFFu, sz, off);
        online_merge(m, s, sx, sy, sz, om, os, osx, osy, osz);
    }

    // ---- cross-warp reduction via shared ----
    __shared__ float red[5][THREADS / 32];   // 16 warps
    const int warp = tid >> 5;
    const int lane = tid & 31;
    if (lane == 0) {
        red[0][warp] = m;
        red[1][warp] = s;
        red[2][warp] = sx;
        red[3][warp] = sy;
        red[4][warp] = sz;
    }
    __syncthreads();

    if (warp == 0) {
        const int NW = THREADS / 32;  // 16
        float fm, fs, fsx, fsy, fsz;
        if (lane < NW) {
            fm  = red[0][lane];
            fs  = red[1][lane];
            fsx = red[2][lane];
            fsy = red[3][lane];
            fsz = red[4][lane];
        } else {
            fm = NEG_BIG; fs = 0.0f; fsx = 0.0f; fsy = 0.0f; fsz = 0.0f;
        }
        #pragma unroll
        for (int off = NW / 2; off > 0; off >>= 1) {
            float om  = __shfl_xor_sync(0xFFFFFFFFu, fm,  off);
            float os  = __shfl_xor_sync(0xFFFFFFFFu, fs,  off);
            float osx = __shfl_xor_sync(0xFFFFFFFFu, fsx, off);
            float osy = __shfl_xor_sync(0xFFFFFFFFu, fsy, off);
            float osz = __shfl_xor_sync(0xFFFFFFFFu, fsz, off);
            online_merge(fm, fs, fsx, fsy, fsz, om, os, osx, osy, osz);
        }
        if (lane == 0) {
            float inv = 1.0f / fs;
            const float invdim = 1.0f / 64.0f;
            out[b * 3 + 0] = fsx * inv * invdim - 0.5f;
            out[b * 3 + 1] = fsy * inv * invdim - 0.5f;
            out[b * 3 + 2] = fsz * inv * invdim - 0.5f;
        }
    }
}

extern "C" void kernel_launch(void* const* d_in, const int* in_sizes, int n_in,
                              void* d_out, int out_size) {
    const float* in = (const float*)d_in[0];
    float* out = (float*)d_out;
    // N*J = 16*24 = 384 (n,j) pairs, one CTA each
    soft_argmax3d_kernel<<<384, THREADS>>>(in, out);
}